// round 2
// baseline (speedup 1.0000x reference)
#include <cuda_runtime.h>
#include <math.h>

#define T_TOK   65536
#define D_EMB   256
#define H_DIM   64
#define N_EXP   10
#define CHUNK   128          // tokens per FFN block (2 passes of 64)
#define XS_STR  68           // padded strides (bank-conflict mitigation, float4-aligned)
#define HS_STR  68
#define NBLK_C  16384        // combine kernel blocks

// ---------------- scratch (static device globals; no runtime allocation) ----
__device__ int   g_count[N_EXP];
__device__ int   g_bucket[N_EXP * T_TOK];                 // (token<<1)|slot
__device__ int   g_eidx [T_TOK * 2];
__device__ float g_gates[T_TOK * 2];
__device__ float g_part [(size_t)T_TOK * 2 * D_EMB];      // per-assignment partial outputs
__device__ float g_kd_part[NBLK_C];

// ---------------- kernel Z: zero expert counters ----------------------------
__global__ void k_zero() {
    if (threadIdx.x < N_EXP) g_count[threadIdx.x] = 0;
}

// ---------------- kernel A: gating (top-2 softmax + bucket build) -----------
__global__ void __launch_bounds__(256) k_gate(const float* __restrict__ x,
                                              const float* __restrict__ wg) {
    __shared__ float wgs[D_EMB * N_EXP];
    int tid = threadIdx.x;
    for (int i = tid; i < D_EMB * N_EXP; i += 256) wgs[i] = wg[i];
    __syncthreads();

    int warp = tid >> 5, lane = tid & 31;
    int t0 = blockIdx.x * 32 + warp * 4;
    for (int r = 0; r < 4; ++r) {
        int t = t0 + r;
        float part[N_EXP];
#pragma unroll
        for (int e = 0; e < N_EXP; ++e) part[e] = 0.f;
#pragma unroll
        for (int dd = 0; dd < 8; ++dd) {
            int d = dd * 32 + lane;
            float xv = x[(size_t)t * D_EMB + d];
#pragma unroll
            for (int e = 0; e < N_EXP; ++e)
                part[e] = fmaf(xv, wgs[d * N_EXP + e], part[e]);
        }
#pragma unroll
        for (int e = 0; e < N_EXP; ++e) {
#pragma unroll
            for (int off = 16; off; off >>= 1)
                part[e] += __shfl_xor_sync(0xffffffffu, part[e], off);
        }
        if (lane == 0) {
            // top-2, ties -> lower index first (jax.lax.top_k semantics)
            float m0 = -1e30f; int e0 = 0;
#pragma unroll
            for (int e = 0; e < N_EXP; ++e) if (part[e] > m0) { m0 = part[e]; e0 = e; }
            float m1 = -1e30f; int e1 = 0;
#pragma unroll
            for (int e = 0; e < N_EXP; ++e) if (e != e0 && part[e] > m1) { m1 = part[e]; e1 = e; }
            float ex = expf(m1 - m0);         // m1 <= m0
            float s  = 1.f + ex;
            float g0 = 1.f / s;
            float g1 = ex / s;
            g_eidx [2 * t]     = e0;  g_gates[2 * t]     = g0;
            g_eidx [2 * t + 1] = e1;  g_gates[2 * t + 1] = g1;
            int p0 = atomicAdd(&g_count[e0], 1);
            g_bucket[e0 * T_TOK + p0] = (t << 1);
            int p1 = atomicAdd(&g_count[e1], 1);
            g_bucket[e1 * T_TOK + p1] = (t << 1) | 1;
        }
    }
}

// ---------------- kernel B: expert-grouped FFN -------------------------------
// grid (512, N_EXP), 128 threads, weights in SMEM, 64-token tiles,
// 4tok x 8h register blocking (fc1) / 4tok x 8o (fc2).
__global__ void __launch_bounds__(128, 1) k_ffn(const float* __restrict__ x,
                                                const float* __restrict__ w1,
                                                const float* __restrict__ b1,
                                                const float* __restrict__ w2,
                                                const float* __restrict__ b2) {
    int e = blockIdx.y;
    int n_total = g_count[e];
    int base = blockIdx.x * CHUNK;
    if (base >= n_total) return;

    extern __shared__ float sm[];
    float* w1s = sm;                              // [256][64]
    float* w2s = w1s + D_EMB * H_DIM;             // [64][256]
    float* xs  = w2s + H_DIM * D_EMB;             // [256][XS_STR] transposed x
    float* hs  = xs  + D_EMB * XS_STR;            // [64][HS_STR]  transposed h
    float* gsh = hs  + H_DIM * HS_STR;            // [64] gates
    int*   ash = (int*)(gsh + 64);                // [64] assignment ids

    int tid = threadIdx.x;

    // stage expert weights (float4, coalesced)
    {
        const float4* w1g = (const float4*)(w1 + (size_t)e * D_EMB * H_DIM);
        float4* d1 = (float4*)w1s;
        for (int i = tid; i < D_EMB * H_DIM / 4; i += 128) d1[i] = w1g[i];
        const float4* w2g = (const float4*)(w2 + (size_t)e * H_DIM * D_EMB);
        float4* d2 = (float4*)w2s;
        for (int i = tid; i < H_DIM * D_EMB / 4; i += 128) d2[i] = w2g[i];
    }

    int tg = tid & 15;    // token group: tokens tg*4 .. tg*4+3
    int hg = tid >> 4;    // 0..7: h/o group of 8

    for (int p = 0; p < CHUNK / 64; ++p) {
        int tbase = base + p * 64;
        if (tbase >= n_total) break;
        int nt = min(64, n_total - tbase);

        __syncthreads();  // weights ready / previous pass fully consumed
        if (tid < 64) {
            if (tid < nt) {
                int a = g_bucket[e * T_TOK + tbase + tid];
                ash[tid] = a;
                gsh[tid] = g_gates[a];
            } else { ash[tid] = -1; gsh[tid] = 0.f; }
        }
        __syncthreads();

        // stage x tile transposed: thread = (s_sub = tid>>6, dq = tid&63)
        {
            int s_sub = tid >> 6;
            int dq = tid & 63;
            for (int it = 0; it < 32; ++it) {
                int s = it * 2 + s_sub;
                float4 v = make_float4(0.f, 0.f, 0.f, 0.f);
                int a = ash[s];
                if (a >= 0) {
                    int t = a >> 1;
                    v = *(const float4*)(x + (size_t)t * D_EMB + dq * 4);
                }
                xs[(dq * 4 + 0) * XS_STR + s] = v.x;
                xs[(dq * 4 + 1) * XS_STR + s] = v.y;
                xs[(dq * 4 + 2) * XS_STR + s] = v.z;
                xs[(dq * 4 + 3) * XS_STR + s] = v.w;
            }
        }
        __syncthreads();

        // ---- fc1: h = relu(x @ W1 + b1), tile 64tok x 64h ----
        float acc[4][8];
#pragma unroll
        for (int i = 0; i < 4; ++i)
#pragma unroll
            for (int j = 0; j < 8; ++j) acc[i][j] = 0.f;

#pragma unroll 4
        for (int d = 0; d < D_EMB; ++d) {
            float4 xv = *(float4*)(xs + d * XS_STR + tg * 4);
            float4 wa = *(float4*)(w1s + d * H_DIM + hg * 8);
            float4 wb = *(float4*)(w1s + d * H_DIM + hg * 8 + 4);
            float xr[4] = {xv.x, xv.y, xv.z, xv.w};
            float wr[8] = {wa.x, wa.y, wa.z, wa.w, wb.x, wb.y, wb.z, wb.w};
#pragma unroll
            for (int i = 0; i < 4; ++i)
#pragma unroll
                for (int j = 0; j < 8; ++j)
                    acc[i][j] = fmaf(xr[i], wr[j], acc[i][j]);
        }
#pragma unroll
        for (int j = 0; j < 8; ++j) {
            float bv = b1[e * H_DIM + hg * 8 + j];
#pragma unroll
            for (int i = 0; i < 4; ++i) {
                float h = acc[i][j] + bv;
                hs[(hg * 8 + j) * HS_STR + tg * 4 + i] = fmaxf(h, 0.f);
            }
        }
        __syncthreads();

        // ---- fc2: part = gate * (h @ W2 + b2), 4 chunks of 64 outputs ----
        int   pidx[4];
        float gt[4];
#pragma unroll
        for (int i = 0; i < 4; ++i) { pidx[i] = ash[tg * 4 + i]; gt[i] = gsh[tg * 4 + i]; }

#pragma unroll 1
        for (int oc = 0; oc < 4; ++oc) {
            int o = oc * 64 + hg * 8;
            float acc2[4][8];
#pragma unroll
            for (int i = 0; i < 4; ++i)
#pragma unroll
                for (int j = 0; j < 8; ++j) acc2[i][j] = 0.f;

#pragma unroll 4
            for (int k = 0; k < H_DIM; ++k) {
                float4 hv = *(float4*)(hs + k * HS_STR + tg * 4);
                float4 wa = *(float4*)(w2s + k * D_EMB + o);
                float4 wb = *(float4*)(w2s + k * D_EMB + o + 4);
                float hr[4] = {hv.x, hv.y, hv.z, hv.w};
                float wr[8] = {wa.x, wa.y, wa.z, wa.w, wb.x, wb.y, wb.z, wb.w};
#pragma unroll
                for (int i = 0; i < 4; ++i)
#pragma unroll
                    for (int j = 0; j < 8; ++j)
                        acc2[i][j] = fmaf(hr[i], wr[j], acc2[i][j]);
            }
            float4 b2a = *(const float4*)(b2 + e * D_EMB + o);
            float4 b2b = *(const float4*)(b2 + e * D_EMB + o + 4);
#pragma unroll
            for (int i = 0; i < 4; ++i) {
                if (pidx[i] >= 0) {
                    float g = gt[i];
                    float4 r0, r1;
                    r0.x = (acc2[i][0] + b2a.x) * g;
                    r0.y = (acc2[i][1] + b2a.y) * g;
                    r0.z = (acc2[i][2] + b2a.z) * g;
                    r0.w = (acc2[i][3] + b2a.w) * g;
                    r1.x = (acc2[i][4] + b2b.x) * g;
                    r1.y = (acc2[i][5] + b2b.y) * g;
                    r1.z = (acc2[i][6] + b2b.z) * g;
                    r1.w = (acc2[i][7] + b2b.w) * g;
                    float* dst = g_part + (size_t)pidx[i] * D_EMB + o;
                    *(float4*)dst       = r0;
                    *(float4*)(dst + 4) = r1;
                }
            }
        }
    }
}

// ---------------- kernel C: combine partials, write out, kd partials --------
__global__ void __launch_bounds__(256) k_combine(float* __restrict__ out) {
    __shared__ float red[256];
    int tid = threadIdx.x;
    size_t f4 = (size_t)blockIdx.x * 256 + tid;   // float4 index
    size_t t  = f4 >> 6;
    int    q  = (int)(f4 & 63);

    float4 a = *((const float4*)(g_part + (t * 2)     * D_EMB) + q);
    float4 b = *((const float4*)(g_part + (t * 2 + 1) * D_EMB) + q);
    float4 y;
    y.x = a.x + b.x; y.y = a.y + b.y; y.z = a.z + b.z; y.w = a.w + b.w;

    float kd = fabsf(y.x) + fabsf(y.y) + fabsf(y.z) + fabsf(y.w);

    float4 o;
    o.x = y.x * 0.5f; o.y = y.y * 0.5f; o.z = y.z * 0.5f; o.w = y.w * 0.5f;
    ((float4*)out)[f4] = o;

    red[tid] = kd;
    __syncthreads();
    for (int s = 128; s; s >>= 1) {
        if (tid < s) red[tid] += red[tid + s];
        __syncthreads();
    }
    if (tid == 0) g_kd_part[blockIdx.x] = red[0];
}

// ---------------- kernel D: finalize loss ------------------------------------
__global__ void __launch_bounds__(256) k_final(float* __restrict__ out, int out_size) {
    __shared__ float red[256];
    __shared__ float impS[N_EXP * 256];
    int tid = threadIdx.x;

    // kd total (deterministic tree)
    float s = 0.f;
    for (int i = tid; i < NBLK_C; i += 256) s += g_kd_part[i];
    red[tid] = s;
    __syncthreads();
    for (int st = 128; st; st >>= 1) {
        if (tid < st) red[tid] += red[tid + st];
        __syncthreads();
    }
    float kd_total = red[0];
    __syncthreads();

    // importance (deterministic tree)
    float imp[N_EXP];
#pragma unroll
    for (int e = 0; e < N_EXP; ++e) imp[e] = 0.f;
    for (int a = tid; a < 2 * T_TOK; a += 256) {
        int e = g_eidx[a];
        float g = g_gates[a];
#pragma unroll
        for (int q = 0; q < N_EXP; ++q) if (q == e) imp[q] += g;
    }
#pragma unroll
    for (int e = 0; e < N_EXP; ++e) impS[e * 256 + tid] = imp[e];
    __syncthreads();
    for (int st = 128; st; st >>= 1) {
        if (tid < st)
#pragma unroll
            for (int e = 0; e < N_EXP; ++e)
                impS[e * 256 + tid] += impS[e * 256 + tid + st];
        __syncthreads();
    }

    if (tid == 0) {
        float iv[N_EXP], lv[N_EXP];
        float si = 0.f, sl = 0.f;
#pragma unroll
        for (int e = 0; e < N_EXP; ++e) {
            iv[e] = impS[e * 256];
            lv[e] = (float)g_count[e];
            si += iv[e]; sl += lv[e];
        }
        float mi = si / (float)N_EXP, ml = sl / (float)N_EXP;
        float vi = 0.f, vl = 0.f;
#pragma unroll
        for (int e = 0; e < N_EXP; ++e) {
            float di = iv[e] - mi; vi += di * di;
            float dl = lv[e] - ml; vl += dl * dl;
        }
        vi /= (float)(N_EXP - 1);
        vl /= (float)(N_EXP - 1);
        float aux = vi / (mi * mi + 1e-10f) + vl / (ml * ml + 1e-10f);
        float kd  = kd_total / (float)((size_t)T_TOK * D_EMB);
        if (out_size > T_TOK * D_EMB)
            out[(size_t)T_TOK * D_EMB] = aux + kd;
    }
}

// ---------------- launch ------------------------------------------------------
extern "C" void kernel_launch(void* const* d_in, const int* in_sizes, int n_in,
                              void* d_out, int out_size) {
    const float* x  = (const float*)d_in[0];
    const float* wg = (const float*)d_in[1];
    const float* w1 = (const float*)d_in[2];
    const float* b1 = (const float*)d_in[3];
    const float* w2 = (const float*)d_in[4];
    const float* b2 = (const float*)d_in[5];
    float* out = (float*)d_out;

    const int SMEM_B = (D_EMB * H_DIM + H_DIM * D_EMB + D_EMB * XS_STR +
                        H_DIM * HS_STR + 64) * (int)sizeof(float) + 64 * (int)sizeof(int);

    cudaFuncSetAttribute(k_ffn, cudaFuncAttributeMaxDynamicSharedMemorySize, SMEM_B);

    k_zero<<<1, 32>>>();
    k_gate<<<T_TOK / 32, 256>>>(x, wg);
    dim3 gB(T_TOK / CHUNK, N_EXP);
    k_ffn<<<gB, 128, SMEM_B>>>(x, w1, b1, w2, b2);
    k_combine<<<NBLK_C, 256>>>(out);
    k_final<<<1, 256>>>(out, out_size);
}

// round 5
// speedup vs baseline: 1.0962x; 1.0962x over previous
#include <cuda_runtime.h>
#include <math.h>

#define T_TOK   65536
#define D_EMB   256
#define H_DIM   64
#define N_EXP   10
#define CHUNK   128          // tokens per FFN block (2 passes of 64)
#define XS_STR  68
#define HS_STR  68
#define NBLK_C  16384

typedef unsigned long long u64;

__device__ __forceinline__ u64 pack2(float lo, float hi) {
    u64 r; asm("mov.b64 %0,{%1,%2};" : "=l"(r) : "f"(lo), "f"(hi)); return r;
}
__device__ __forceinline__ void ffma2(u64& d, u64 a, u64 b) {
    asm("fma.rn.f32x2 %0,%1,%2,%0;" : "+l"(d) : "l"(a), "l"(b));
}
__device__ __forceinline__ u64 add2(u64 a, u64 b) {
    u64 r; asm("add.rn.f32x2 %0,%1,%2;" : "=l"(r) : "l"(a), "l"(b)); return r;
}
__device__ __forceinline__ u64 mul2(u64 a, u64 b) {
    u64 r; asm("mul.rn.f32x2 %0,%1,%2;" : "=l"(r) : "l"(a), "l"(b)); return r;
}
__device__ __forceinline__ float2 unpack2(u64 v) {
    float2 r; asm("mov.b64 {%0,%1},%2;" : "=f"(r.x), "=f"(r.y) : "l"(v)); return r;
}

// ---------------- scratch ----------------------------------------------------
__device__ int   g_count[N_EXP];
__device__ int   g_bucket[N_EXP * T_TOK];
__device__ int   g_eidx [T_TOK * 2];
__device__ float g_gates[T_TOK * 2];
__device__ float g_part [(size_t)T_TOK * 2 * D_EMB];
__device__ float g_kd_part[NBLK_C];

// ---------------- kernel Z ----------------------------------------------------
__global__ void k_zero() {
    if (threadIdx.x < N_EXP) g_count[threadIdx.x] = 0;
}

// ---------------- kernel A: gating ---------------------------------------------
__global__ void __launch_bounds__(256) k_gate(const float* __restrict__ x,
                                              const float* __restrict__ wg) {
    __shared__ float wgs[D_EMB * N_EXP];
    int tid = threadIdx.x;
    for (int i = tid; i < D_EMB * N_EXP; i += 256) wgs[i] = wg[i];
    __syncthreads();

    int warp = tid >> 5, lane = tid & 31;
    int t0 = blockIdx.x * 32 + warp * 4;
    for (int r = 0; r < 4; ++r) {
        int t = t0 + r;
        float part[N_EXP];
#pragma unroll
        for (int e = 0; e < N_EXP; ++e) part[e] = 0.f;
#pragma unroll
        for (int dd = 0; dd < 8; ++dd) {
            int d = dd * 32 + lane;
            float xv = x[(size_t)t * D_EMB + d];
#pragma unroll
            for (int e = 0; e < N_EXP; ++e)
                part[e] = fmaf(xv, wgs[d * N_EXP + e], part[e]);
        }
#pragma unroll
        for (int e = 0; e < N_EXP; ++e) {
#pragma unroll
            for (int off = 16; off; off >>= 1)
                part[e] += __shfl_xor_sync(0xffffffffu, part[e], off);
        }
        if (lane == 0) {
            float m0 = -1e30f; int e0 = 0;
#pragma unroll
            for (int e = 0; e < N_EXP; ++e) if (part[e] > m0) { m0 = part[e]; e0 = e; }
            float m1 = -1e30f; int e1 = 0;
#pragma unroll
            for (int e = 0; e < N_EXP; ++e) if (e != e0 && part[e] > m1) { m1 = part[e]; e1 = e; }
            float ex = expf(m1 - m0);
            float s  = 1.f + ex;
            float g0 = 1.f / s;
            float g1 = ex / s;
            g_eidx [2 * t]     = e0;  g_gates[2 * t]     = g0;
            g_eidx [2 * t + 1] = e1;  g_gates[2 * t + 1] = g1;
            int p0 = atomicAdd(&g_count[e0], 1);
            g_bucket[e0 * T_TOK + p0] = (t << 1);
            int p1 = atomicAdd(&g_count[e1], 1);
            g_bucket[e1 * T_TOK + p1] = (t << 1) | 1;
        }
    }
}

// ---------------- kernel B: expert-grouped FFN (256 thr, f32x2 packed) --------
// 64-token passes. fc1: 64tok x 64h, fc2: 4 chunks of 64tok x 64o.
// thread: tg = tid&31 (token pair), hg = tid>>5 (warp -> 8 h/o values).
__global__ void __launch_bounds__(256, 1) k_ffn(const float* __restrict__ x,
                                                const float* __restrict__ w1,
                                                const float* __restrict__ b1,
                                                const float* __restrict__ w2,
                                                const float* __restrict__ b2) {
    int e = blockIdx.y;
    int n_total = g_count[e];
    int base = blockIdx.x * CHUNK;
    if (base >= n_total) return;

    extern __shared__ float sm[];
    float* w1s = sm;                              // [256][64]
    float* w2s = w1s + D_EMB * H_DIM;             // [64][256]
    float* xs  = w2s + H_DIM * D_EMB;             // [256][XS_STR] transposed x
    float* hs  = xs  + D_EMB * XS_STR;            // [64][HS_STR]  transposed h
    float* gsh = hs  + H_DIM * HS_STR;            // [64]
    int*   ash = (int*)(gsh + 64);                // [64]

    int tid = threadIdx.x;
    int tg = tid & 31;    // token pair idx: tokens tg*2, tg*2+1
    int hg = tid >> 5;    // warp id 0..7 -> h/o group of 8

    // stage expert weights
    {
        const float4* w1g = (const float4*)(w1 + (size_t)e * D_EMB * H_DIM);
        float4* d1 = (float4*)w1s;
        for (int i = tid; i < D_EMB * H_DIM / 4; i += 256) d1[i] = w1g[i];
        const float4* w2g = (const float4*)(w2 + (size_t)e * H_DIM * D_EMB);
        float4* d2 = (float4*)w2s;
        for (int i = tid; i < H_DIM * D_EMB / 4; i += 256) d2[i] = w2g[i];
    }

    // per-thread bias registers (lane-invariant per warp, L1-cached)
    float2 b1p[4];
#pragma unroll
    for (int j = 0; j < 4; ++j)
        b1p[j] = *(const float2*)(b1 + e * H_DIM + hg * 8 + j * 2);

    int s_stage  = tid & 63;    // staging: token slot
    int dq_stage = tid >> 6;    // staging: 0..3

    for (int p = 0; p < CHUNK / 64; ++p) {
        int tbase = base + p * 64;
        if (tbase >= n_total) break;
        int nt = min(64, n_total - tbase);

        __syncthreads();  // weights ready / previous pass consumed
        if (tid < 64) {
            if (tid < nt) {
                int a = g_bucket[e * T_TOK + tbase + tid];
                ash[tid] = a;
                gsh[tid] = g_gates[a];
            } else { ash[tid] = -1; gsh[tid] = 0.f; }
        }
        __syncthreads();

        // stage x tile transposed
        {
            int a = ash[s_stage];
            const float4* xrow = (a >= 0)
                ? (const float4*)(x + (size_t)(a >> 1) * D_EMB) : (const float4*)0;
#pragma unroll 4
            for (int it = 0; it < 16; ++it) {
                int d4 = it * 4 + dq_stage;      // 0..63
                float4 v = make_float4(0.f, 0.f, 0.f, 0.f);
                if (a >= 0) v = xrow[d4];
                xs[(d4 * 4 + 0) * XS_STR + s_stage] = v.x;
                xs[(d4 * 4 + 1) * XS_STR + s_stage] = v.y;
                xs[(d4 * 4 + 2) * XS_STR + s_stage] = v.z;
                xs[(d4 * 4 + 3) * XS_STR + s_stage] = v.w;
            }
        }
        __syncthreads();

        // ---- fc1: 2tok x 8h per thread, packed f32x2 ----
        {
            u64 acc[2][4];
#pragma unroll
            for (int i = 0; i < 2; ++i)
#pragma unroll
                for (int j = 0; j < 4; ++j) acc[i][j] = 0ULL;

#pragma unroll 4
            for (int d = 0; d < D_EMB; ++d) {
                float2 xv = *(const float2*)(xs + d * XS_STR + tg * 2);
                u64 a0 = pack2(xv.x, xv.x);
                u64 a1 = pack2(xv.y, xv.y);
                ulonglong2 wA = *(const ulonglong2*)(w1s + d * H_DIM + hg * 8);
                ulonglong2 wB = *(const ulonglong2*)(w1s + d * H_DIM + hg * 8 + 4);
                ffma2(acc[0][0], a0, wA.x); ffma2(acc[0][1], a0, wA.y);
                ffma2(acc[0][2], a0, wB.x); ffma2(acc[0][3], a0, wB.y);
                ffma2(acc[1][0], a1, wA.x); ffma2(acc[1][1], a1, wA.y);
                ffma2(acc[1][2], a1, wB.x); ffma2(acc[1][3], a1, wB.y);
            }
#pragma unroll
            for (int i = 0; i < 2; ++i)
#pragma unroll
                for (int j = 0; j < 4; ++j) {
                    float2 h = unpack2(acc[i][j]);
                    h.x = fmaxf(h.x + b1p[j].x, 0.f);
                    h.y = fmaxf(h.y + b1p[j].y, 0.f);
                    int hb = hg * 8 + j * 2;
                    hs[(hb)     * HS_STR + tg * 2 + i] = h.x;
                    hs[(hb + 1) * HS_STR + tg * 2 + i] = h.y;
                }
        }
        __syncthreads();

        // ---- fc2: part = gate * (h @ W2 + b2) ----
        int a0i = ash[tg * 2], a1i = ash[tg * 2 + 1];
        float g0 = gsh[tg * 2], g1 = gsh[tg * 2 + 1];
        u64 gp0 = pack2(g0, g0), gp1 = pack2(g1, g1);

#pragma unroll 1
        for (int oc = 0; oc < 4; ++oc) {
            int o = oc * 64 + hg * 8;
            u64 acc[2][4];
#pragma unroll
            for (int i = 0; i < 2; ++i)
#pragma unroll
                for (int j = 0; j < 4; ++j) acc[i][j] = 0ULL;

#pragma unroll 4
            for (int k = 0; k < H_DIM; ++k) {
                float2 hv = *(const float2*)(hs + k * HS_STR + tg * 2);
                u64 a0 = pack2(hv.x, hv.x);
                u64 a1 = pack2(hv.y, hv.y);
                ulonglong2 wA = *(const ulonglong2*)(w2s + k * D_EMB + o);
                ulonglong2 wB = *(const ulonglong2*)(w2s + k * D_EMB + o + 4);
                ffma2(acc[0][0], a0, wA.x); ffma2(acc[0][1], a0, wA.y);
                ffma2(acc[0][2], a0, wB.x); ffma2(acc[0][3], a0, wB.y);
                ffma2(acc[1][0], a1, wA.x); ffma2(acc[1][1], a1, wA.y);
                ffma2(acc[1][2], a1, wB.x); ffma2(acc[1][3], a1, wB.y);
            }
            ulonglong2 bA = *(const ulonglong2*)(b2 + e * D_EMB + o);
            ulonglong2 bB = *(const ulonglong2*)(b2 + e * D_EMB + o + 4);
            if (a0i >= 0) {
                ulonglong2 r0, r1;
                r0.x = mul2(add2(acc[0][0], bA.x), gp0);
                r0.y = mul2(add2(acc[0][1], bA.y), gp0);
                r1.x = mul2(add2(acc[0][2], bB.x), gp0);
                r1.y = mul2(add2(acc[0][3], bB.y), gp0);
                float* dst = g_part + (size_t)a0i * D_EMB + o;
                *(ulonglong2*)dst       = r0;
                *(ulonglong2*)(dst + 4) = r1;
            }
            if (a1i >= 0) {
                ulonglong2 r0, r1;
                r0.x = mul2(add2(acc[1][0], bA.x), gp1);
                r0.y = mul2(add2(acc[1][1], bA.y), gp1);
                r1.x = mul2(add2(acc[1][2], bB.x), gp1);
                r1.y = mul2(add2(acc[1][3], bB.y), gp1);
                float* dst = g_part + (size_t)a1i * D_EMB + o;
                *(ulonglong2*)dst       = r0;
                *(ulonglong2*)(dst + 4) = r1;
            }
        }
    }
}

// ---------------- kernel C: combine -------------------------------------------
__global__ void __launch_bounds__(256) k_combine(float* __restrict__ out) {
    __shared__ float red[256];
    int tid = threadIdx.x;
    size_t f4 = (size_t)blockIdx.x * 256 + tid;
    size_t t  = f4 >> 6;
    int    q  = (int)(f4 & 63);

    float4 a = *((const float4*)(g_part + (t * 2)     * D_EMB) + q);
    float4 b = *((const float4*)(g_part + (t * 2 + 1) * D_EMB) + q);
    float4 y;
    y.x = a.x + b.x; y.y = a.y + b.y; y.z = a.z + b.z; y.w = a.w + b.w;

    float kd = fabsf(y.x) + fabsf(y.y) + fabsf(y.z) + fabsf(y.w);

    float4 o;
    o.x = y.x * 0.5f; o.y = y.y * 0.5f; o.z = y.z * 0.5f; o.w = y.w * 0.5f;
    ((float4*)out)[f4] = o;

    red[tid] = kd;
    __syncthreads();
    for (int s = 128; s; s >>= 1) {
        if (tid < s) red[tid] += red[tid + s];
        __syncthreads();
    }
    if (tid == 0) g_kd_part[blockIdx.x] = red[0];
}

// ---------------- kernel D: finalize loss ---------------------------------------
__global__ void __launch_bounds__(256) k_final(float* __restrict__ out, int out_size) {
    __shared__ float red[256];
    __shared__ float impS[N_EXP * 256];
    int tid = threadIdx.x;

    float s = 0.f;
    for (int i = tid; i < NBLK_C; i += 256) s += g_kd_part[i];
    red[tid] = s;
    __syncthreads();
    for (int st = 128; st; st >>= 1) {
        if (tid < st) red[tid] += red[tid + st];
        __syncthreads();
    }
    float kd_total = red[0];
    __syncthreads();

    float imp[N_EXP];
#pragma unroll
    for (int e = 0; e < N_EXP; ++e) imp[e] = 0.f;
    for (int a = tid; a < 2 * T_TOK; a += 256) {
        int e = g_eidx[a];
        float g = g_gates[a];
#pragma unroll
        for (int q = 0; q < N_EXP; ++q) if (q == e) imp[q] += g;
    }
#pragma unroll
    for (int e = 0; e < N_EXP; ++e) impS[e * 256 + tid] = imp[e];
    __syncthreads();
    for (int st = 128; st; st >>= 1) {
        if (tid < st)
#pragma unroll
            for (int e = 0; e < N_EXP; ++e)
                impS[e * 256 + tid] += impS[e * 256 + tid + st];
        __syncthreads();
    }

    if (tid == 0) {
        float iv[N_EXP], lv[N_EXP];
        float si = 0.f, sl = 0.f;
#pragma unroll
        for (int e = 0; e < N_EXP; ++e) {
            iv[e] = impS[e * 256];
            lv[e] = (float)g_count[e];
            si += iv[e]; sl += lv[e];
        }
        float mi = si / (float)N_EXP, ml = sl / (float)N_EXP;
        float vi = 0.f, vl = 0.f;
#pragma unroll
        for (int e = 0; e < N_EXP; ++e) {
            float di = iv[e] - mi; vi += di * di;
            float dl = lv[e] - ml; vl += dl * dl;
        }
        vi /= (float)(N_EXP - 1);
        vl /= (float)(N_EXP - 1);
        float aux = vi / (mi * mi + 1e-10f) + vl / (ml * ml + 1e-10f);
        float kd  = kd_total / (float)((size_t)T_TOK * D_EMB);
        if (out_size > T_TOK * D_EMB)
            out[(size_t)T_TOK * D_EMB] = aux + kd;
    }
}

// ---------------- launch --------------------------------------------------------
extern "C" void kernel_launch(void* const* d_in, const int* in_sizes, int n_in,
                              void* d_out, int out_size) {
    const float* x  = (const float*)d_in[0];
    const float* wg = (const float*)d_in[1];
    const float* w1 = (const float*)d_in[2];
    const float* b1 = (const float*)d_in[3];
    const float* w2 = (const float*)d_in[4];
    const float* b2 = (const float*)d_in[5];
    float* out = (float*)d_out;

    const int SMEM_B = (D_EMB * H_DIM + H_DIM * D_EMB + D_EMB * XS_STR +
                        H_DIM * HS_STR + 64) * (int)sizeof(float) + 64 * (int)sizeof(int);

    cudaFuncSetAttribute(k_ffn, cudaFuncAttributeMaxDynamicSharedMemorySize, SMEM_B);

    k_zero<<<1, 32>>>();
    k_gate<<<T_TOK / 32, 256>>>(x, wg);
    dim3 gB(T_TOK / CHUNK, N_EXP);
    k_ffn<<<gB, 256, SMEM_B>>>(x, w1, b1, w2, b2);
    k_combine<<<NBLK_C, 256>>>(out);
    k_final<<<1, 256>>>(out, out_size);
}